// round 17
// baseline (speedup 1.0000x reference)
#include <cuda_runtime.h>
#include <cuda_fp16.h>
#include <cstdint>

// ============================================================================
// OutlierAwareLinear: y = x @ W^T + b, then per-token outlier-aware fake quant.
// GEMM: 3-term FP16 split (hi/lo) on mma.sync.m16n8k16.f16.f32 (R15 structure:
// W pre-split -> cp.async; A split in-GEMM; term-major MMA issue).
// THIS ROUND: the quant pass is FUSED into the GEMM. Each m-block (128 rows)
// is quantized by the LAST of its 8 N-CTAs to finish (per-m-block atomic
// counter). 127/128 quant jobs overlap the GEMM's remaining waves; only the
// final m-block's quant (~L2-bound, few us) is exposed. Removes the 39.6us
// standalone quant launch.
// ============================================================================

#define M_DIM 16384
#define K_DIM 2048
#define N_DIM 2048
#define BM 128
#define BN 256
#define BK 64                    // 64 fp16 = 128 bytes per row
#define NCHUNKS (K_DIM / BK)     // 32
#define N_CTAS_PER_MBLOCK (N_DIM / BN)   // 8

// smem per buffer: Ahi 16K | Alo 16K | Bhi 32K | Blo 32K = 96KB; 2 buffers
#define OFF_AHI 0
#define OFF_ALO 16384
#define OFF_BHI 32768
#define OFF_BLO 65536
#define BUF_STRIDE 98304
#define SMEM_TOTAL (2 * BUF_STRIDE)   // 192 KB

// ---- global fp16 hi/lo scratch for W + completion counters ----
__device__ __half g_Whi[(size_t)N_DIM * K_DIM];   // 8 MB
__device__ __half g_Wlo[(size_t)N_DIM * K_DIM];   // 8 MB
__device__ int    g_cnt[M_DIM / BM];              // 128 counters

__device__ __forceinline__ uint32_t smem_u32(const void* p) {
    return (uint32_t)__cvta_generic_to_shared(p);
}
__device__ __forceinline__ uint32_t swz(uint32_t off) {
    return off ^ ((off >> 3) & 0x70);
}
__device__ __forceinline__ void ldsm_x4(uint32_t r[4], uint32_t addr) {
    asm volatile("ldmatrix.sync.aligned.m8n8.x4.shared.b16 {%0,%1,%2,%3}, [%4];"
                 : "=r"(r[0]), "=r"(r[1]), "=r"(r[2]), "=r"(r[3]) : "r"(addr));
}
__device__ __forceinline__ void mma_f16(float c[4], const uint32_t a[4],
                                        const uint32_t* b) {
    asm volatile(
        "mma.sync.aligned.m16n8k16.row.col.f32.f16.f16.f32 "
        "{%0,%1,%2,%3}, {%4,%5,%6,%7}, {%8,%9}, {%0,%1,%2,%3};"
        : "+f"(c[0]), "+f"(c[1]), "+f"(c[2]), "+f"(c[3])
        : "r"(a[0]), "r"(a[1]), "r"(a[2]), "r"(a[3]), "r"(b[0]), "r"(b[1]));
}
__device__ __forceinline__ void cp16(uint32_t dst, const void* src) {
    asm volatile("cp.async.cg.shared.global [%0], [%1], 16;" :: "r"(dst), "l"(src));
}
#define CP_COMMIT() asm volatile("cp.async.commit_group;" ::: "memory")
#define CP_WAIT1()  asm volatile("cp.async.wait_group 1;" ::: "memory")

#define QMAX 127.0f
#define OUTLIER_T 3.0f
#define Q_EPS 1e-6f

// ---------------------------------------------------------------------------
// W split kernel (also resets the per-m-block counters for this replay).
// ---------------------------------------------------------------------------
#define NW4 ((size_t)N_DIM * K_DIM / 4)

__global__ __launch_bounds__(256)
void oal_wsplit_kernel(const float4* __restrict__ w4) {
    if (blockIdx.x == 0 && threadIdx.x < M_DIM / BM) g_cnt[threadIdx.x] = 0;

    const size_t i = (size_t)blockIdx.x * blockDim.x + threadIdx.x;
    if (i >= NW4) return;
    float4 v = w4[i];
    __half2* hi = (__half2*)g_Whi;
    __half2* lo = (__half2*)g_Wlo;
    const size_t o = i * 2;

    __half2 h0 = __floats2half2_rn(v.x, v.y);
    __half2 h1 = __floats2half2_rn(v.z, v.w);
    float2 f0 = __half22float2(h0);
    float2 f1 = __half22float2(h1);
    hi[o]     = h0;
    hi[o + 1] = h1;
    lo[o]     = __floats2half2_rn(v.x - f0.x, v.y - f0.y);
    lo[o + 1] = __floats2half2_rn(v.z - f1.x, v.w - f1.y);
}

// ---------------------------------------------------------------------------
// GEMM + fused quant.
// ---------------------------------------------------------------------------
__global__ __launch_bounds__(256, 1)
void oal_gemm_f16(const float* __restrict__ A,     // [M,K] fp32
                  const float* __restrict__ bias,
                  float* __restrict__ Y) {
    extern __shared__ char smem[];
    const uint32_t sb = smem_u32(smem);

    const int tid = threadIdx.x;
    const int lane = tid & 31;
    const int wid = tid >> 5;
    const int warp_m = (wid & 3) * 32;
    const int warp_n = (wid >> 2) * 128;
    const int block_m = blockIdx.y * BM;
    const int block_n = blockIdx.x * BN;

    const uint32_t swmask = (lane & 7) << 4;
    uint32_t a_off[2];
#pragma unroll
    for (int mt = 0; mt < 2; mt++) {
        uint32_t row = warp_m + mt * 16 + (lane & 15);
        a_off[mt] = row * 128 + (lane >> 4) * 16;
    }
    uint32_t b_off[8];
#pragma unroll
    for (int ntp = 0; ntp < 8; ntp++) {
        uint32_t n = warp_n + ntp * 16 + ((lane >> 4) & 1) * 8 + (lane & 7);
        b_off[ntp] = n * 128 + ((lane >> 3) & 1) * 16;
    }

    const int r8 = tid >> 3;
    const int c16 = (tid & 7) * 16;
    const int kseg8 = (tid & 7) * 8;

    const float*  Af  = A     + (size_t)(block_m + r8) * K_DIM + kseg8;
    const __half* Bhi = g_Whi + (size_t)(block_n + r8) * K_DIM + kseg8;
    const __half* Blo = g_Wlo + (size_t)(block_n + r8) * K_DIM + kseg8;

    float acc[2][16][4];
#pragma unroll
    for (int mt = 0; mt < 2; mt++)
#pragma unroll
        for (int nt = 0; nt < 16; nt++)
#pragma unroll
            for (int j = 0; j < 4; j++) acc[mt][nt][j] = 0.0f;

    float4 st[4][2];

    auto a_load = [&](int c) {
        const int k0 = c * BK;
#pragma unroll
        for (int p = 0; p < 4; p++) {
            const float* src = Af + (size_t)(p * 32) * K_DIM + k0;
            st[p][0] = *(const float4*)(src);
            st[p][1] = *(const float4*)(src + 4);
        }
    };
    auto a_store = [&](int b) {
        char* dst = smem + b * BUF_STRIDE;
#pragma unroll
        for (int p = 0; p < 4; p++) {
            const uint32_t sw = swz((r8 + p * 32) * 128 + c16);
            float4 u = st[p][0], v = st[p][1];
            __half2 h0 = __floats2half2_rn(u.x, u.y);
            __half2 h1 = __floats2half2_rn(u.z, u.w);
            __half2 h2 = __floats2half2_rn(v.x, v.y);
            __half2 h3 = __floats2half2_rn(v.z, v.w);
            float2 f0 = __half22float2(h0), f1 = __half22float2(h1);
            float2 f2 = __half22float2(h2), f3 = __half22float2(h3);
            __half2 l0 = __floats2half2_rn(u.x - f0.x, u.y - f0.y);
            __half2 l1 = __floats2half2_rn(u.z - f1.x, u.w - f1.y);
            __half2 l2 = __floats2half2_rn(v.x - f2.x, v.y - f2.y);
            __half2 l3 = __floats2half2_rn(v.z - f3.x, v.w - f3.y);
            uint4 hv = make_uint4(*(uint32_t*)&h0, *(uint32_t*)&h1,
                                  *(uint32_t*)&h2, *(uint32_t*)&h3);
            uint4 lv = make_uint4(*(uint32_t*)&l0, *(uint32_t*)&l1,
                                  *(uint32_t*)&l2, *(uint32_t*)&l3);
            *(uint4*)(dst + OFF_AHI + sw) = hv;
            *(uint4*)(dst + OFF_ALO + sw) = lv;
        }
    };
    auto b_fill = [&](int c, int b) {
        const uint32_t base = sb + b * BUF_STRIDE;
        const int k0 = c * BK;
#pragma unroll
        for (int p = 0; p < 8; p++) {
            const uint32_t sw = swz((r8 + p * 32) * 128 + c16);
            cp16(base + OFF_BHI + sw, Bhi + (size_t)(p * 32) * K_DIM + k0);
            cp16(base + OFF_BLO + sw, Blo + (size_t)(p * 32) * K_DIM + k0);
        }
    };

    a_load(0); a_store(0);
    b_fill(0, 0); CP_COMMIT();
    a_load(1); a_store(1);
    b_fill(1, 1); CP_COMMIT();
    a_load(2);

    for (int c = 0; c < NCHUNKS; c++) {
        const int b = c & 1;
        const uint32_t cur = sb + b * BUF_STRIDE;

        CP_WAIT1();
        __syncthreads();

#pragma unroll
        for (int ks = 0; ks < 4; ks++) {
            uint32_t ah[2][4], al[2][4];
#pragma unroll
            for (int mt = 0; mt < 2; mt++) {
                const uint32_t ao = (a_off[mt] + ks * 32) ^ swmask;
                ldsm_x4(ah[mt], cur + OFF_AHI + ao);
                ldsm_x4(al[mt], cur + OFF_ALO + ao);
            }
#pragma unroll
            for (int ntp = 0; ntp < 8; ntp++) {
                const uint32_t bo = (b_off[ntp] + ks * 32) ^ swmask;
                uint32_t bh[4], bl[4];
                ldsm_x4(bh, cur + OFF_BHI + bo);
                ldsm_x4(bl, cur + OFF_BLO + bo);
#pragma unroll
                for (int t = 0; t < 2; t++)
#pragma unroll
                    for (int mt = 0; mt < 2; mt++)
                        mma_f16(acc[mt][2 * ntp + t], ah[mt], bh + 2 * t);  // hi*hi
#pragma unroll
                for (int t = 0; t < 2; t++)
#pragma unroll
                    for (int mt = 0; mt < 2; mt++)
                        mma_f16(acc[mt][2 * ntp + t], ah[mt], bl + 2 * t);  // hi*lo
#pragma unroll
                for (int t = 0; t < 2; t++)
#pragma unroll
                    for (int mt = 0; mt < 2; mt++)
                        mma_f16(acc[mt][2 * ntp + t], al[mt], bh + 2 * t);  // lo*hi
            }
        }

        __syncthreads();
        if (c + 2 < NCHUNKS) {
            a_store(b);
            b_fill(c + 2, b);
        }
        CP_COMMIT();
        if (c + 3 < NCHUNKS) a_load(c + 3);
    }

    // ---- epilogue: acc -> gmem with bias ----
    const int g = lane >> 2;
    const int t4 = lane & 3;
#pragma unroll
    for (int mt = 0; mt < 2; mt++) {
        const int m0 = block_m + warp_m + mt * 16 + g;
#pragma unroll
        for (int nt = 0; nt < 16; nt++) {
            const int n0 = block_n + warp_n + nt * 8 + t4 * 2;
            const float2 bb = *(const float2*)(bias + n0);
            float2 v0, v1;
            v0.x = acc[mt][nt][0] + bb.x;
            v0.y = acc[mt][nt][1] + bb.y;
            v1.x = acc[mt][nt][2] + bb.x;
            v1.y = acc[mt][nt][3] + bb.y;
            *(float2*)(Y + (size_t)m0 * N_DIM + n0) = v0;
            *(float2*)(Y + (size_t)(m0 + 8) * N_DIM + n0) = v1;
        }
    }

    // ---- fused quant: last CTA of this m-block quantizes its 128 rows ----
    __threadfence();                      // release our Y stores
    __syncthreads();
    __shared__ int s_prior;
    if (tid == 0) s_prior = atomicAdd(&g_cnt[blockIdx.y], 1);
    __syncthreads();
    if (s_prior != N_CTAS_PER_MBLOCK - 1) return;
    __threadfence();                      // acquire peers' Y stores

    // 8 warps x 16 rows each; per row: pass1 stats, pass2 quantize (L2-hot)
    for (int r = 0; r < 16; r++) {
        const int row = block_m + wid * 16 + r;
        float4* y4 = (float4*)(Y + (size_t)row * N_DIM);

        float s = 0.0f, ss = 0.0f, amax = 0.0f;
#pragma unroll
        for (int j = 0; j < 16; j++) {
            float4 u = y4[lane + j * 32];
            s += u.x + u.y + u.z + u.w;
            ss = fmaf(u.x, u.x, ss); ss = fmaf(u.y, u.y, ss);
            ss = fmaf(u.z, u.z, ss); ss = fmaf(u.w, u.w, ss);
            amax = fmaxf(amax, fmaxf(fmaxf(fabsf(u.x), fabsf(u.y)),
                                     fmaxf(fabsf(u.z), fabsf(u.w))));
        }
#pragma unroll
        for (int off = 16; off > 0; off >>= 1) {
            s += __shfl_xor_sync(0xFFFFFFFFu, s, off);
            ss += __shfl_xor_sync(0xFFFFFFFFu, ss, off);
            amax = fmaxf(amax, __shfl_xor_sync(0xFFFFFFFFu, amax, off));
        }

        const float inv_d = 1.0f / (float)N_DIM;
        const float mean = s * inv_d;
        const float var = fmaxf(ss * inv_d - mean * mean, 0.0f);
        const float thr = OUTLIER_T * sqrtf(var);
        const float scale = fmaxf(fminf(amax, thr) / QMAX, Q_EPS);
        const float inv_scale = 1.0f / scale;

#pragma unroll
        for (int j = 0; j < 16; j++) {
            float4 u = y4[lane + j * 32];
            float* e = (float*)&u;
#pragma unroll
            for (int k = 0; k < 4; k++) {
                float x = e[k];
                float cl = fminf(fmaxf(x, -thr), thr);
                float fq = rintf(cl * inv_scale) * scale;
                e[k] = (fabsf(x) > thr) ? x : fq;
            }
            y4[lane + j * 32] = u;
        }
    }
}

// ---------------------------------------------------------------------------

extern "C" void kernel_launch(void* const* d_in, const int* in_sizes, int n_in,
                              void* d_out, int out_size) {
    const float* x = (const float*)d_in[0];
    const float* W = (const float*)d_in[1];
    const float* b = (const float*)d_in[2];
    float* out = (float*)d_out;

    cudaFuncSetAttribute(oal_gemm_f16, cudaFuncAttributeMaxDynamicSharedMemorySize, SMEM_TOTAL);

    // 1) split W into fp16 hi/lo (+ reset m-block counters for this replay)
    const int sblocks = (int)((NW4 + 255) / 256);
    oal_wsplit_kernel<<<sblocks, 256>>>((const float4*)W);

    // 2) GEMM with fused per-m-block quant
    dim3 ggrid(N_DIM / BN, M_DIM / BM);   // (8, 128)
    oal_gemm_f16<<<ggrid, 256, SMEM_TOTAL>>>(x, b, out);
}